// round 4
// baseline (speedup 1.0000x reference)
#include <cuda_runtime.h>

#define Bsz   32768
#define Edim  128
#define Fdim  128
#define Gdim  256
#define NFdim 256
#define EPSv  1e-5f

typedef unsigned long long ull;

// ---------------- scratch (device globals: allocation-free contract) ----------------
__device__ float g_VALS[(size_t)Bsz * 4 * Edim];   // ent() results, slots 0..3   (64 MB)
__device__ float g_X   [(size_t)Bsz * 6 * Fdim];   // post conv+BN+relu           (100 MB)
__device__ float g_C   [6 * Fdim];                 // folded role+bias+BN constant
__device__ float g_WcT [Edim * Fdim];              // conv_W val-half, transposed, BN-scaled

// ---------------- packed fp32x2 helpers (sm_100+) ----------------
__device__ __forceinline__ void ffma2(ull &d, ull a, ull b){
    asm("fma.rn.f32x2 %0, %1, %2, %0;" : "+l"(d) : "l"(a), "l"(b));
}
__device__ __forceinline__ ull dup2(float x){
    ull r; asm("mov.b64 %0, {%1, %1};" : "=l"(r) : "f"(x)); return r;
}
__device__ __forceinline__ float2 upk(ull v){
    float2 f; asm("mov.b64 {%0, %1}, %2;" : "=f"(f.x), "=f"(f.y) : "l"(v)); return f;
}

// ---------------- prep: fold roles + BN into constants ----------------
// blocks 0..5: C[a][f] = (role_emb[ROLES[a]]·conv_W[f,:128] + conv_b - mean)*scale + beta
// block 6:     WcT[e][f] = conv_W[f][128+e] * scale[f]
__global__ void kprep(const float* __restrict__ role_emb, const float* __restrict__ conv_W,
                      const float* __restrict__ conv_b, const float* __restrict__ gam,
                      const float* __restrict__ bet, const float* __restrict__ mea,
                      const float* __restrict__ var)
{
    int f = threadIdx.x;
    float sc = gam[f] * rsqrtf(var[f] + EPSv);
    int blk = blockIdx.x;
    if (blk < 6) {
        const int roles[6] = {0, 1, 2, 3, 4, 6};
        __shared__ float rs[Edim];
        rs[f] = role_emb[roles[blk] * Edim + f];
        __syncthreads();
        float d = 0.f;
        const float* cw = conv_W + f * 2 * Edim;
        #pragma unroll 8
        for (int e = 0; e < Edim; e++) d += rs[e] * cw[e];
        g_C[blk * Fdim + f] = (d + conv_b[f] - mea[f]) * sc + bet[f];
    } else {
        for (int e = 0; e < Edim; e++)
            g_WcT[e * Fdim + f] = conv_W[f * 2 * Edim + Edim + e] * sc;
    }
}

// ---------------- stage 1: gathered ent GEMM ----------------
// rows R in [0,4B): b = R>>2, slot j = R&3  (0:a, 1:event, 2:b, 3:c)
// VALS[R] = relu(nf[id] @ node_W + node_b) + entity_emb[id]
// tile: 128 rows x 128 cols, K=256 in 8 chunks; thread micro-tile 8m x 8n (f32x2 pairs on m)
__global__ __launch_bounds__(256, 2) void kent(
    const int* __restrict__ aid, const int* __restrict__ evid,
    const int* __restrict__ bid, const int* __restrict__ cid,
    const float* __restrict__ nf, const float* __restrict__ ee,
    const float* __restrict__ nW, const float* __restrict__ nbias)
{
    __shared__ int sid[128];
    __shared__ __align__(16) float As[32 * 130];
    __shared__ __align__(16) float Bs[32 * 128];
    int t = threadIdx.x;
    int r0 = blockIdx.x * 128;
    if (t < 128) {
        int R = r0 + t;
        int b = R >> 2, j = R & 3;
        const int* p = (j == 0) ? aid : (j == 1) ? evid : (j == 2) ? bid : cid;
        sid[t] = p[b];
    }
    __syncthreads();
    int mb = t >> 4, nb = t & 15;
    int m0 = mb * 8, n0 = nb * 8;
    ull acc[4][8];
    #pragma unroll
    for (int i = 0; i < 4; i++)
        #pragma unroll
        for (int j = 0; j < 8; j++) acc[i][j] = 0ULL;

    for (int kc = 0; kc < 8; kc++) {
        int k0 = kc * 32;
        #pragma unroll
        for (int it = 0; it < 16; it++) {
            int idx = t + it * 256;
            int m = idx >> 5, k = idx & 31;
            As[k * 130 + m] = nf[(size_t)sid[m] * NFdim + k0 + k];
        }
        {
            const float4* src = (const float4*)(nW + k0 * Fdim);
            float4* dst = (float4*)Bs;
            #pragma unroll
            for (int it = 0; it < 4; it++) dst[t + it * 256] = src[t + it * 256];
        }
        __syncthreads();
        #pragma unroll 4
        for (int kk = 0; kk < 32; kk++) {
            const ull* ap = (const ull*)(As + kk * 130 + m0);
            ull a0 = ap[0], a1 = ap[1], a2 = ap[2], a3 = ap[3];
            const float4* bp = (const float4*)(Bs + kk * 128 + n0);
            float4 blo = bp[0], bhi = bp[1];
            float bf[8] = {blo.x, blo.y, blo.z, blo.w, bhi.x, bhi.y, bhi.z, bhi.w};
            #pragma unroll
            for (int j = 0; j < 8; j++) {
                ull b2 = dup2(bf[j]);
                ffma2(acc[0][j], a0, b2);
                ffma2(acc[1][j], a1, b2);
                ffma2(acc[2][j], a2, b2);
                ffma2(acc[3][j], a3, b2);
            }
        }
        __syncthreads();
    }

    float4 nb0 = *(const float4*)(nbias + n0);
    float4 nb1 = *(const float4*)(nbias + n0 + 4);
    #pragma unroll
    for (int p = 0; p < 4; p++) {
        float lo[8], hi[8];
        #pragma unroll
        for (int j = 0; j < 8; j++) { float2 v = upk(acc[p][j]); lo[j] = v.x; hi[j] = v.y; }
        #pragma unroll
        for (int h = 0; h < 2; h++) {
            float vv[8];
            #pragma unroll
            for (int j = 0; j < 8; j++) vv[j] = h ? hi[j] : lo[j];
            int m = m0 + 2 * p + h;
            int R = r0 + m;
            const float4* e4 = (const float4*)(ee + (size_t)sid[m] * Edim + n0);
            float4 e0 = e4[0], e1 = e4[1];
            float4 o0, o1;
            o0.x = fmaxf(vv[0] + nb0.x, 0.f) + e0.x;
            o0.y = fmaxf(vv[1] + nb0.y, 0.f) + e0.y;
            o0.z = fmaxf(vv[2] + nb0.z, 0.f) + e0.z;
            o0.w = fmaxf(vv[3] + nb0.w, 0.f) + e0.w;
            o1.x = fmaxf(vv[4] + nb1.x, 0.f) + e1.x;
            o1.y = fmaxf(vv[5] + nb1.y, 0.f) + e1.y;
            o1.z = fmaxf(vv[6] + nb1.z, 0.f) + e1.z;
            o1.w = fmaxf(vv[7] + nb1.w, 0.f) + e1.w;
            float4* dst = (float4*)(g_VALS + (size_t)R * Edim + n0);
            dst[0] = o0; dst[1] = o1;
        }
    }
}

// ---------------- stage 2: conv + BN + relu ----------------
// rows r in [0,6B): b=r/6, slot s=r%6. A row source: VALS (s<4) / cond (s==4) / text (s==5)
// X[r][f] = relu( A[r]·WcT[:,f] + C[s][f] )
__global__ __launch_bounds__(256, 2) void kconv(const float* __restrict__ cond,
                                                const float* __restrict__ text)
{
    __shared__ const float* srcp[128];
    __shared__ int sslot[128];
    __shared__ __align__(16) float As[32 * 130];
    __shared__ __align__(16) float Bs[32 * 128];
    int t = threadIdx.x;
    int r0 = blockIdx.x * 128;
    if (t < 128) {
        int r = r0 + t;
        int b = r / 6, s = r - b * 6;
        const float* p;
        if (s < 4)      p = g_VALS + ((size_t)b * 4 + s) * Edim;
        else if (s == 4) p = cond + (size_t)b * Edim;
        else             p = text + (size_t)b * Edim;
        srcp[t] = p; sslot[t] = s;
    }
    __syncthreads();
    int mb = t >> 4, nb = t & 15;
    int m0 = mb * 8, n0 = nb * 8;
    ull acc[4][8];
    #pragma unroll
    for (int i = 0; i < 4; i++)
        #pragma unroll
        for (int j = 0; j < 8; j++) acc[i][j] = 0ULL;

    for (int kc = 0; kc < 4; kc++) {
        int k0 = kc * 32;
        #pragma unroll
        for (int it = 0; it < 16; it++) {
            int idx = t + it * 256;
            int m = idx >> 5, k = idx & 31;
            As[k * 130 + m] = srcp[m][k0 + k];
        }
        {
            const float4* src = (const float4*)(g_WcT + k0 * Fdim);
            float4* dst = (float4*)Bs;
            #pragma unroll
            for (int it = 0; it < 4; it++) dst[t + it * 256] = src[t + it * 256];
        }
        __syncthreads();
        #pragma unroll 4
        for (int kk = 0; kk < 32; kk++) {
            const ull* ap = (const ull*)(As + kk * 130 + m0);
            ull a0 = ap[0], a1 = ap[1], a2 = ap[2], a3 = ap[3];
            const float4* bp = (const float4*)(Bs + kk * 128 + n0);
            float4 blo = bp[0], bhi = bp[1];
            float bf[8] = {blo.x, blo.y, blo.z, blo.w, bhi.x, bhi.y, bhi.z, bhi.w};
            #pragma unroll
            for (int j = 0; j < 8; j++) {
                ull b2 = dup2(bf[j]);
                ffma2(acc[0][j], a0, b2);
                ffma2(acc[1][j], a1, b2);
                ffma2(acc[2][j], a2, b2);
                ffma2(acc[3][j], a3, b2);
            }
        }
        __syncthreads();
    }

    #pragma unroll
    for (int p = 0; p < 4; p++) {
        float lo[8], hi[8];
        #pragma unroll
        for (int j = 0; j < 8; j++) { float2 v = upk(acc[p][j]); lo[j] = v.x; hi[j] = v.y; }
        #pragma unroll
        for (int h = 0; h < 2; h++) {
            float vv[8];
            #pragma unroll
            for (int j = 0; j < 8; j++) vv[j] = h ? hi[j] : lo[j];
            int m = m0 + 2 * p + h;
            int r = r0 + m;
            const float4* c4 = (const float4*)(g_C + sslot[m] * Fdim + n0);
            float4 c0 = c4[0], c1 = c4[1];
            float4 o0, o1;
            o0.x = fmaxf(vv[0] + c0.x, 0.f);
            o0.y = fmaxf(vv[1] + c0.y, 0.f);
            o0.z = fmaxf(vv[2] + c0.z, 0.f);
            o0.w = fmaxf(vv[3] + c0.w, 0.f);
            o1.x = fmaxf(vv[4] + c1.x, 0.f);
            o1.y = fmaxf(vv[5] + c1.y, 0.f);
            o1.z = fmaxf(vv[6] + c1.z, 0.f);
            o1.w = fmaxf(vv[7] + c1.w, 0.f);
            float4* dst = (float4*)(g_X + (size_t)r * Fdim + n0);
            dst[0] = o0; dst[1] = o1;
        }
    }
}

// ---------------- stage 3: u/v GEMM + min over 6 + relu out ----------------
// out[b][g] = relu( min_a (X[b,a]·W1[:,g]) + min_a (X[b,a]·W2[:,g]) + gb[g] )
// block: 16 batch rows (96 X-rows) x 128 g-cols; pass h=0 -> W1 (gW rows 0..127),
// h=1 -> W2 (rows 128..255). Thread: one batch row (6 X-rows = 3 f32x2 pairs) x 8 g.
__global__ __launch_bounds__(256, 2) void kuv(const float* __restrict__ gW,
                                              const float* __restrict__ gb,
                                              float* __restrict__ out)
{
    __shared__ __align__(16) float As[32 * 98];
    __shared__ __align__(16) float Bs[32 * 128];
    int t = threadIdx.x;
    int r0 = blockIdx.x * 96;
    int g0 = blockIdx.y * 128;
    int mb = t >> 4, nb = t & 15;
    int m0 = mb * 6, n0 = nb * 8;
    float mins[2][8];

    #pragma unroll
    for (int h = 0; h < 2; h++) {
        ull acc[3][8];
        #pragma unroll
        for (int i = 0; i < 3; i++)
            #pragma unroll
            for (int j = 0; j < 8; j++) acc[i][j] = 0ULL;

        for (int kc = 0; kc < 4; kc++) {
            #pragma unroll
            for (int it = 0; it < 12; it++) {
                int idx = t + it * 256;
                int m = idx >> 5, k = idx & 31;
                As[k * 98 + m] = g_X[(size_t)(r0 + m) * Fdim + kc * 32 + k];
            }
            #pragma unroll
            for (int it = 0; it < 16; it++) {
                int idx = t + it * 256;
                int k = idx >> 7, n = idx & 127;
                Bs[idx] = gW[(size_t)(h * Fdim + kc * 32 + k) * Gdim + g0 + n];
            }
            __syncthreads();
            #pragma unroll 4
            for (int kk = 0; kk < 32; kk++) {
                const ull* ap = (const ull*)(As + kk * 98 + m0);
                ull a0 = ap[0], a1 = ap[1], a2 = ap[2];
                const float4* bp = (const float4*)(Bs + kk * 128 + n0);
                float4 blo = bp[0], bhi = bp[1];
                float bf[8] = {blo.x, blo.y, blo.z, blo.w, bhi.x, bhi.y, bhi.z, bhi.w};
                #pragma unroll
                for (int j = 0; j < 8; j++) {
                    ull b2 = dup2(bf[j]);
                    ffma2(acc[0][j], a0, b2);
                    ffma2(acc[1][j], a1, b2);
                    ffma2(acc[2][j], a2, b2);
                }
            }
            __syncthreads();
        }
        #pragma unroll
        for (int j = 0; j < 8; j++) {
            float2 v0 = upk(acc[0][j]), v1 = upk(acc[1][j]), v2 = upk(acc[2][j]);
            mins[h][j] = fminf(fminf(fminf(v0.x, v0.y), fminf(v1.x, v1.y)),
                               fminf(v2.x, v2.y));
        }
    }

    int bg = blockIdx.x * 16 + mb;
    const float4* gb4 = (const float4*)(gb + g0 + n0);
    float4 b0 = gb4[0], b1 = gb4[1];
    float4 o0, o1;
    o0.x = fmaxf(mins[0][0] + mins[1][0] + b0.x, 0.f);
    o0.y = fmaxf(mins[0][1] + mins[1][1] + b0.y, 0.f);
    o0.z = fmaxf(mins[0][2] + mins[1][2] + b0.z, 0.f);
    o0.w = fmaxf(mins[0][3] + mins[1][3] + b0.w, 0.f);
    o1.x = fmaxf(mins[0][4] + mins[1][4] + b1.x, 0.f);
    o1.y = fmaxf(mins[0][5] + mins[1][5] + b1.y, 0.f);
    o1.z = fmaxf(mins[0][6] + mins[1][6] + b1.z, 0.f);
    o1.w = fmaxf(mins[0][7] + mins[1][7] + b1.w, 0.f);
    float4* dst = (float4*)(out + (size_t)bg * Gdim + g0 + n0);
    dst[0] = o0; dst[1] = o1;
}

// ---------------- launcher ----------------
extern "C" void kernel_launch(void* const* d_in, const int* in_sizes, int n_in,
                              void* d_out, int out_size)
{
    const int*   a_ids = (const int*)d_in[0];
    const int*   b_ids = (const int*)d_in[1];
    const int*   c_ids = (const int*)d_in[2];
    const int*   e_ids = (const int*)d_in[3];
    const float* nf    = (const float*)d_in[4];
    const float* cond  = (const float*)d_in[5];
    const float* text  = (const float*)d_in[6];
    const float* ee    = (const float*)d_in[7];
    const float* re    = (const float*)d_in[8];
    const float* nW    = (const float*)d_in[9];
    const float* nbias = (const float*)d_in[10];
    const float* cW    = (const float*)d_in[11];
    const float* cb    = (const float*)d_in[12];
    const float* gam   = (const float*)d_in[13];
    const float* bet   = (const float*)d_in[14];
    const float* mea   = (const float*)d_in[15];
    const float* var   = (const float*)d_in[16];
    const float* gW    = (const float*)d_in[17];
    const float* gbias = (const float*)d_in[18];
    float* out = (float*)d_out;

    kprep<<<7, 128>>>(re, cW, cb, gam, bet, mea, var);
    kent<<<(4 * Bsz) / 128, 256>>>(a_ids, e_ids, b_ids, c_ids, nf, ee, nW, nbias);
    kconv<<<(6 * Bsz) / 128, 256>>>(cond, text);
    kuv<<<dim3(Bsz / 16, 2), 256>>>(gW, gbias, out);
}